// round 13
// baseline (speedup 1.0000x reference)
#include <cuda_runtime.h>
#include <cuda_fp16.h>
#include <cstdint>

#define NN 100000
#define EE 1600000
#define IN_F 128
#define HID_F 256
#define OUT_F 47
#define T2S 48

// ---------------- scratch ---------------------------------------------------
__device__ float g_tmp[(size_t)NN * T2S];           // layer-2 direct term (fp32)
__device__ __align__(16) __half g_xf  [(size_t)NN * IN_F];
__device__ __align__(16) __half g_aggf[(size_t)NN * HID_F];
__device__ __align__(16) __half g_hf  [(size_t)NN * HID_F];
__device__ __align__(16) __half g_h2f [(size_t)NN * HID_F];
__device__ __align__(16) __half g_part[(size_t)NN * HID_F]; // self-GEMM partial
__device__ __align__(16) __half g_t2  [(size_t)NN * T2S];
__device__ int   g_count [NN];
__device__ float g_invdeg[NN];
__device__ int   g_rowptr[NN + 1];
__device__ int   g_cursor[NN];
__device__ int   g_csrsrc[EE];
__device__ int   g_bsums [128];
__device__ int   g_is64;

// weight table, fp16, transposed [N,K] row-major
#define WB_TOTAL 229376
__device__ __align__(16) __half g_wf[WB_TOTAL];

#define MT 782
#define GFB (MT * 2)                     // 1564 gemm blocks in fused grid
#define FUSED_GRID (GFB * 17)            // 26588 (1/17 gemm, rest agg)

// ---------------- prep ------------------------------------------------------
__global__ void k_prep(const int* ei_raw,
                       const float* Wl0, const float* Wr0,
                       const float* Wl1, const float* Wr1,
                       const float* Wl2, const float* Wr2) {
    int idx = blockIdx.x * blockDim.x + threadIdx.x;
    if (idx < NN) g_count[idx] = 0;
    if (idx == 0) {
        int is64 = 1;
        for (int i = 0; i < 256; i++)
            if (ei_raw[2 * i + 1] != 0) { is64 = 0; break; }
        g_is64 = is64;
    }
    if (idx < WB_TOTAL) {
        float w;
        if (idx < 32768)       { int l = idx;          int n = l >> 7, k = l & 127; w = Wl0[k * 256 + n]; }
        else if (idx < 65536)  { int l = idx - 32768;  int n = l >> 7, k = l & 127; w = Wr0[k * 256 + n]; }
        else if (idx < 131072) { int l = idx - 65536;  int n = l >> 8, k = l & 255; w = Wl1[k * 256 + n]; }
        else if (idx < 196608) { int l = idx - 131072; int n = l >> 8, k = l & 255; w = Wr1[k * 256 + n]; }
        else if (idx < 212992) { int l = idx - 196608; int n = l >> 8, k = l & 255; w = (n < OUT_F) ? Wl2[k * OUT_F + n] : 0.f; }
        else                   { int l = idx - 212992; int n = l >> 8, k = l & 255; w = (n < OUT_F) ? Wr2[k * OUT_F + n] : 0.f; }
        g_wf[idx] = __float2half_rn(w);
    }
}

// x fp32 -> fp16 plane
__global__ void k_cvt(const float4* __restrict__ X, uint2* __restrict__ O, int n4) {
    int i = blockIdx.x * blockDim.x + threadIdx.x;
    if (i >= n4) return;
    float4 v = X[i];
    __half2 p0 = __floats2half2_rn(v.x, v.y);
    __half2 p1 = __floats2half2_rn(v.z, v.w);
    uint2 o;
    o.x = *(uint32_t*)&p0;
    o.y = *(uint32_t*)&p1;
    O[i] = o;
}

// ---------------- CSR build -------------------------------------------------
__device__ __forceinline__ int load_edge(const void* ei, long long idx, int is64) {
    if (is64) return (int)((const long long*)ei)[idx];
    return ((const int*)ei)[idx];
}

__global__ void k_hist(const void* ei) {
    int e = blockIdx.x * blockDim.x + threadIdx.x;
    if (e < EE) {
        int d = load_edge(ei, (long long)EE + e, g_is64);
        atomicAdd(&g_count[d], 1);
    }
}

__global__ void k_scan1() {
    __shared__ int sh[1024];
    int i = blockIdx.x * 1024 + threadIdx.x;
    int v = (i < NN) ? g_count[i] : 0;
    sh[threadIdx.x] = v;
    __syncthreads();
    for (int off = 1; off < 1024; off <<= 1) {
        int t = (threadIdx.x >= off) ? sh[threadIdx.x - off] : 0;
        __syncthreads();
        sh[threadIdx.x] += t;
        __syncthreads();
    }
    if (i < NN) g_rowptr[i] = sh[threadIdx.x] - v;
    if (threadIdx.x == 1023) g_bsums[blockIdx.x] = sh[1023];
}

__global__ void k_scan23() {
    __shared__ int base;
    if (threadIdx.x == 0) {
        int run = 0;
        for (int b = 0; b < (int)blockIdx.x; b++) run += g_bsums[b];
        base = run;
    }
    __syncthreads();
    int i = blockIdx.x * 1024 + threadIdx.x;
    if (i < NN) {
        int r = g_rowptr[i] + base;
        g_rowptr[i] = r;
        g_cursor[i] = r;
        g_invdeg[i] = 1.0f / (float)max(g_count[i], 1);
    }
    if (i == 0) g_rowptr[NN] = EE;
}

__global__ void k_scatter(const void* ei) {
    int e = blockIdx.x * blockDim.x + threadIdx.x;
    if (e < EE) {
        int is64 = g_is64;
        int d = load_edge(ei, (long long)EE + e, is64);
        int s = load_edge(ei, e, is64);
        int p = atomicAdd(&g_cursor[d], 1);
        g_csrsrc[p] = s;
    }
}

// ---------------- GEMM building blocks ---------------------------------------
__device__ __forceinline__ void mma16816(float* c, const uint32_t* a, const uint32_t* b) {
    asm volatile(
        "mma.sync.aligned.m16n8k16.row.col.f32.f16.f16.f32 "
        "{%0,%1,%2,%3}, {%4,%5,%6,%7}, {%8,%9}, {%0,%1,%2,%3};"
        : "+f"(c[0]), "+f"(c[1]), "+f"(c[2]), "+f"(c[3])
        : "r"(a[0]), "r"(a[1]), "r"(a[2]), "r"(a[3]), "r"(b[0]), "r"(b[1]));
}
__device__ __forceinline__ void ldmx4(uint32_t& r0, uint32_t& r1, uint32_t& r2, uint32_t& r3,
                                      uint32_t addr) {
    asm volatile("ldmatrix.sync.aligned.m8n8.x4.shared.b16 {%0,%1,%2,%3}, [%4];"
                 : "=r"(r0), "=r"(r1), "=r"(r2), "=r"(r3) : "r"(addr));
}
__device__ __forceinline__ void cp16(uint32_t dst, const void* src) {
    asm volatile("cp.async.cg.shared.global [%0], [%1], 16;" :: "r"(dst), "l"(src));
}
__device__ __forceinline__ void cp_commit() {
    asm volatile("cp.async.commit_group;" ::: "memory");
}
template <int N> __device__ __forceinline__ void cp_wait() {
    asm volatile("cp.async.wait_group %0;" :: "n"(N) : "memory");
}
__device__ __forceinline__ uint32_t smem_u32(const void* p) {
    uint32_t a;
    asm("{ .reg .u64 t; cvta.to.shared.u64 t, %1; cvt.u32.u64 %0, t; }"
        : "=r"(a) : "l"(p));
    return a;
}

#define APL 10240                        // plane: 128 rows x 80B (64B payload)
#define STAGE (2 * APL)                  // A, B
#define GEMM_SMEM (4 * STAGE)            // 81920 (4 stages)

// Core 128x128 tile GEMM loop: loads A/B chunks via cp.async, computes acc.
// Caller provides rowBase/colBlk; acc is [4][8][4].
struct GemmCore {
    template <typename EPI>
    static __device__ __forceinline__ void run(
        const __half* A, int ldA, int K, const __half* B, int ldB,
        int rowBase, int colBlk, int M, char* smem, int tid, EPI epi) {
        const uint32_t sbase = smem_u32(smem);
        const int wid  = tid >> 5;
        const int lane = tid & 31;
        const int wm   = wid >> 1;
        const int wn   = wid & 1;
        const uint32_t aoff = (uint32_t)((lane & 15) * 80 + (lane >> 4) * 16);
        const uint32_t boff = (uint32_t)(((lane & 7) + ((lane >> 4) & 1) * 8) * 80 +
                                         ((lane >> 3) & 1) * 16);
        float acc[4][8][4];
#pragma unroll
        for (int mt = 0; mt < 4; mt++)
#pragma unroll
            for (int nt = 0; nt < 8; nt++)
#pragma unroll
                for (int j = 0; j < 4; j++) acc[mt][nt][j] = 0.f;

        const int NC = K / 32;
        auto issue = [&](int c) {
            const uint32_t sb = sbase + (c & 3) * STAGE;
            const int k0 = c * 32;
#pragma unroll
            for (int i = tid; i < 1024; i += 128) {
                int p = i >> 9, r = (i >> 2) & 127, ch = i & 3;
                const __half* g;
                if (p == 0) {
                    int gr = min(rowBase + r, M - 1);
                    g = A + (size_t)gr * ldA + k0 + ch * 8;
                } else {
                    g = B + (size_t)(colBlk + r) * ldB + k0 + ch * 8;
                }
                cp16(sb + p * APL + r * 80 + ch * 16, g);
            }
            cp_commit();
        };

        issue(0);
        issue(1);
        for (int c = 0; c < NC; c++) {
            if (c + 2 < NC)      { issue(c + 2); cp_wait<2>(); }
            else if (c + 1 < NC) { cp_wait<1>(); }
            else                 { cp_wait<0>(); }
            __syncthreads();
            const uint32_t sA = sbase + (c & 3) * STAGE;
            const uint32_t sB = sA + APL;
#pragma unroll
            for (int ks = 0; ks < 2; ks++) {
                const uint32_t kshift = (uint32_t)(ks * 32);
                uint32_t a[4][4];
#pragma unroll
                for (int mt = 0; mt < 4; mt++) {
                    uint32_t addr = sA + (uint32_t)((64 * wm + mt * 16) * 80) + aoff + kshift;
                    ldmx4(a[mt][0], a[mt][1], a[mt][2], a[mt][3], addr);
                }
                uint32_t b[8][2];
#pragma unroll
                for (int ntp = 0; ntp < 4; ntp++) {
                    uint32_t addr = sB + (uint32_t)((64 * wn + ntp * 16) * 80) + boff + kshift;
                    ldmx4(b[2 * ntp][0], b[2 * ntp][1], b[2 * ntp + 1][0], b[2 * ntp + 1][1], addr);
                }
#pragma unroll
                for (int mt = 0; mt < 4; mt++)
#pragma unroll
                    for (int nt = 0; nt < 8; nt++)
                        mma16816(acc[mt][nt], a[mt], b[nt]);
            }
        }

        const int gid = lane >> 2, tig = lane & 3;
#pragma unroll
        for (int mt = 0; mt < 4; mt++) {
            int r0 = rowBase + 64 * wm + mt * 16 + gid;
#pragma unroll
            for (int nt = 0; nt < 8; nt++) {
                int gc = colBlk + 64 * wn + nt * 8 + 2 * tig;
#pragma unroll
                for (int half = 0; half < 2; half++) {
                    int rr = r0 + half * 8;
                    if (rr >= M) continue;
                    epi(rr, gc, acc[mt][nt][half * 2 + 0], acc[mt][nt][half * 2 + 1]);
                }
            }
        }
    }
};

// ---------------- fused: self-GEMM (1/17 blocks) + aggregation ----------------
template <int AGGW>
__global__ void __launch_bounds__(128, 2)
k_fused(const __half* __restrict__ Ag, int ldA, int K,
        const __half* __restrict__ Bw, int ldB,
        __half* __restrict__ Pout,
        const __half* __restrict__ Xa, __half* __restrict__ Oa, int M) {
    extern __shared__ __align__(16) char smem[];
    const int bx = blockIdx.x;
    const int tid = threadIdx.x;
    if ((bx % 17) == 0 && (bx / 17) < GFB) {
        // ---- self-GEMM block ----
        int g = bx / 17;
        int rowBase = (g >> 1) * 128;
        int colBlk  = (g & 1) * 128;
        GemmCore::run(Ag, ldA, K, Bw, ldB, rowBase, colBlk, M, smem, tid,
            [&](int rr, int gc, float v0, float v1) {
                __half2 hp = __floats2half2_rn(v0, v1);
                *(__half2*)(Pout + (size_t)rr * HID_F + gc) = hp;
            });
    } else {
        // ---- aggregation block: 4 warps, 1 node each, 8-edge unroll ----
        int agg_id = bx - (bx + 16) / 17;
        int w = agg_id * 4 + (tid >> 5);
        int lane = tid & 31;
        if (w >= NN) return;
        int beg = g_rowptr[w], end = g_rowptr[w + 1];
        if (AGGW == 128) {
            float4 acc = make_float4(0.f, 0.f, 0.f, 0.f);
            int e = beg;
            for (; e + 8 <= end; e += 8) {
                uint2 u[8];
#pragma unroll
                for (int j = 0; j < 8; j++)
                    u[j] = ((const uint2*)(Xa + (size_t)g_csrsrc[e + j] * IN_F))[lane];
#pragma unroll
                for (int j = 0; j < 8; j++) {
                    float2 a = __half22float2(*(__half2*)&u[j].x);
                    float2 b = __half22float2(*(__half2*)&u[j].y);
                    acc.x += a.x; acc.y += a.y; acc.z += b.x; acc.w += b.y;
                }
            }
            for (; e < end; e++) {
                uint2 u = ((const uint2*)(Xa + (size_t)g_csrsrc[e] * IN_F))[lane];
                float2 a = __half22float2(*(__half2*)&u.x);
                float2 b = __half22float2(*(__half2*)&u.y);
                acc.x += a.x; acc.y += a.y; acc.z += b.x; acc.w += b.y;
            }
            float inv = g_invdeg[w];
            __half2 p0 = __floats2half2_rn(acc.x * inv, acc.y * inv);
            __half2 p1 = __floats2half2_rn(acc.z * inv, acc.w * inv);
            uint2 o;
            o.x = *(uint32_t*)&p0;
            o.y = *(uint32_t*)&p1;
            ((uint2*)(Oa + (size_t)w * IN_F))[lane] = o;
        } else {
            float acc[8];
#pragma unroll
            for (int j = 0; j < 8; j++) acc[j] = 0.f;
            int e = beg;
            for (; e + 8 <= end; e += 8) {
                uint4 u[8];
#pragma unroll
                for (int j = 0; j < 8; j++)
                    u[j] = ((const uint4*)(Xa + (size_t)g_csrsrc[e + j] * HID_F))[lane];
#pragma unroll
                for (int j = 0; j < 8; j++) {
#pragma unroll
                    for (int q = 0; q < 4; q++) {
                        uint32_t ww = (&u[j].x)[q];
                        float2 f = __half22float2(*(__half2*)&ww);
                        acc[2 * q] += f.x; acc[2 * q + 1] += f.y;
                    }
                }
            }
            for (; e < end; e++) {
                uint4 u = ((const uint4*)(Xa + (size_t)g_csrsrc[e] * HID_F))[lane];
#pragma unroll
                for (int q = 0; q < 4; q++) {
                    uint32_t ww = (&u.x)[q];
                    float2 f = __half22float2(*(__half2*)&ww);
                    acc[2 * q] += f.x; acc[2 * q + 1] += f.y;
                }
            }
            float inv = g_invdeg[w];
            uint4 o;
#pragma unroll
            for (int q = 0; q < 4; q++) {
                __half2 p = __floats2half2_rn(acc[2 * q] * inv, acc[2 * q + 1] * inv);
                (&o.x)[q] = *(uint32_t*)&p;
            }
            ((uint4*)(Oa + (size_t)w * HID_F))[lane] = o;
        }
    }
}

// ---------------- agg-GEMM: agg@Wl + bias + partial (+pre) -> relu plane -----
template <bool WPRE>
__global__ void __launch_bounds__(128, 2)
k_mma_l(const __half* __restrict__ A, int ldA, int K,
        const __half* __restrict__ B, int ldB,
        const float* __restrict__ bias, const __half* __restrict__ Part,
        float* __restrict__ Cpre, __half* __restrict__ Ch, int M) {
    extern __shared__ __align__(16) char smem[];
    int rowBase = blockIdx.x * 128;
    int colBlk  = blockIdx.y * 128;
    GemmCore::run(A, ldA, K, B, ldB, rowBase, colBlk, M, smem, threadIdx.x,
        [&](int rr, int gc, float v0, float v1) {
            float2 pv = __half22float2(*(const __half2*)(Part + (size_t)rr * HID_F + gc));
            v0 += bias[gc] + pv.x;
            v1 += bias[gc + 1] + pv.y;
            if (WPRE) {
                float* p = Cpre + (size_t)rr * HID_F + gc;
                p[0] = v0; p[1] = v1;
            }
            v0 = fmaxf(v0, 0.f); v1 = fmaxf(v1, 0.f);
            __half2 hp = __floats2half2_rn(v0, v1);
            *(__half2*)(Ch + (size_t)rr * HID_F + gc) = hp;
        });
}

// ---------------- layer-2 GEMM: split epilogue -------------------------------
__global__ void __launch_bounds__(128, 2)
k_mma2(const __half* __restrict__ A, int ldA, int K,
       const __half* __restrict__ B, int ldB,
       const float* __restrict__ bias,
       __half* __restrict__ Ct2, float* __restrict__ Caux, int M) {
    extern __shared__ __align__(16) char smem[];
    int rowBase = blockIdx.x * 128;
    GemmCore::run(A, ldA, K, B, ldB, rowBase, 0, M, smem, threadIdx.x,
        [&](int rr, int gc, float v0, float v1) {
#pragma unroll
            for (int q = 0; q < 2; q++) {
                int col = gc + q;
                float v = q ? v1 : v0;
                if (col < 64) {
                    if (col < OUT_F) Ct2[(size_t)rr * T2S + col] = __float2half_rn(v);
                } else {
                    int c2 = col - 64;
                    if (c2 < OUT_F) Caux[(size_t)rr * T2S + c2] = v + bias[c2];
                }
            }
        });
}

// mean-agg over t2 (fp16, stride T2S) + tmp (fp32) -> out (stride 47)
__global__ void k_agg47_add(const __half* __restrict__ T2, const float* __restrict__ Tmp,
                            float* __restrict__ out) {
    int w = (blockIdx.x * blockDim.x + threadIdx.x) >> 5;
    int lane = threadIdx.x & 31;
    if (w >= NN || lane >= 24) return;
    int beg = g_rowptr[w], end = g_rowptr[w + 1];
    float a0 = 0.f, a1 = 0.f;
    int e = beg;
    for (; e + 4 <= end; e += 4) {
        int s0 = g_csrsrc[e], s1 = g_csrsrc[e + 1];
        int s2 = g_csrsrc[e + 2], s3 = g_csrsrc[e + 3];
        uint32_t u0 = *(const uint32_t*)(T2 + (size_t)s0 * T2S + lane * 2);
        uint32_t u1 = *(const uint32_t*)(T2 + (size_t)s1 * T2S + lane * 2);
        uint32_t u2 = *(const uint32_t*)(T2 + (size_t)s2 * T2S + lane * 2);
        uint32_t u3 = *(const uint32_t*)(T2 + (size_t)s3 * T2S + lane * 2);
        float2 f0 = __half22float2(*(__half2*)&u0);
        float2 f1 = __half22float2(*(__half2*)&u1);
        float2 f2 = __half22float2(*(__half2*)&u2);
        float2 f3 = __half22float2(*(__half2*)&u3);
        a0 += f0.x + f1.x + f2.x + f3.x;
        a1 += f0.y + f1.y + f2.y + f3.y;
    }
    for (; e < end; e++) {
        uint32_t u = *(const uint32_t*)(T2 + (size_t)g_csrsrc[e] * T2S + lane * 2);
        float2 f = __half22float2(*(__half2*)&u);
        a0 += f.x; a1 += f.y;
    }
    float inv = g_invdeg[w];
    const float* tr = Tmp + (size_t)w * T2S;
    float* orow = out + (size_t)w * OUT_F;
    int c0 = lane * 2, c1 = c0 + 1;
    orow[c0] = a0 * inv + tr[c0];
    if (c1 < OUT_F) orow[c1] = a1 * inv + tr[c1];
}

// ---------------- launch ----------------------------------------------------
extern "C" void kernel_launch(void* const* d_in, const int* in_sizes, int n_in,
                              void* d_out, int out_size) {
    const float* x   = (const float*)d_in[0];
    const void*  ei  = d_in[1];
    const float* Wl0 = (const float*)d_in[2];
    const float* bl0 = (const float*)d_in[3];
    const float* Wr0 = (const float*)d_in[4];
    const float* Wl1 = (const float*)d_in[5];
    const float* bl1 = (const float*)d_in[6];
    const float* Wr1 = (const float*)d_in[7];
    const float* Wl2 = (const float*)d_in[8];
    const float* bl2 = (const float*)d_in[9];
    const float* Wr2 = (const float*)d_in[10];

    float* out  = (float*)d_out;
    float* hout = out + (size_t)NN * OUT_F;

    float* p_tmp;
    __half *xf, *aggf, *hf, *h2f, *part, *t2, *wf;
    cudaGetSymbolAddress((void**)&p_tmp, g_tmp);
    cudaGetSymbolAddress((void**)&xf,   g_xf);
    cudaGetSymbolAddress((void**)&aggf, g_aggf);
    cudaGetSymbolAddress((void**)&hf,   g_hf);
    cudaGetSymbolAddress((void**)&h2f,  g_h2f);
    cudaGetSymbolAddress((void**)&part, g_part);
    cudaGetSymbolAddress((void**)&t2,   g_t2);
    cudaGetSymbolAddress((void**)&wf,   g_wf);

    cudaFuncSetAttribute(k_fused<128>, cudaFuncAttributeMaxDynamicSharedMemorySize, GEMM_SMEM);
    cudaFuncSetAttribute(k_fused<256>, cudaFuncAttributeMaxDynamicSharedMemorySize, GEMM_SMEM);
    cudaFuncSetAttribute(k_mma_l<false>, cudaFuncAttributeMaxDynamicSharedMemorySize, GEMM_SMEM);
    cudaFuncSetAttribute(k_mma_l<true>,  cudaFuncAttributeMaxDynamicSharedMemorySize, GEMM_SMEM);
    cudaFuncSetAttribute(k_mma2, cudaFuncAttributeMaxDynamicSharedMemorySize, GEMM_SMEM);

    const int AGG_BLKS = (NN + 7) / 8;

    // prep + CSR build
    k_prep<<<(WB_TOTAL + 255) / 256, 256>>>((const int*)ei, Wl0, Wr0, Wl1, Wr1, Wl2, Wr2);
    k_cvt<<<(NN * IN_F / 4 + 255) / 256, 256>>>((const float4*)x, (uint2*)xf, NN * IN_F / 4);
    k_hist<<<(EE + 255) / 256, 256>>>(ei);
    k_scan1<<<(NN + 1023) / 1024, 1024>>>();
    k_scan23<<<(NN + 1023) / 1024, 1024>>>();
    k_scatter<<<(EE + 255) / 256, 256>>>(ei);

    // layer 0: fused [self-GEMM x@Wr0 -> part | agg0] then agg@Wl0+bl0+part
    k_fused<128><<<FUSED_GRID, 128, GEMM_SMEM>>>(
        xf, IN_F, IN_F, wf + 32768, IN_F, part, xf, aggf, NN);
    k_mma_l<false><<<dim3(MT, 2), 128, GEMM_SMEM>>>(
        aggf, IN_F, IN_F, wf + 0, IN_F, bl0, part, nullptr, hf, NN);

    // layer 1: fused [h@Wr1 -> part | agg1] then agg@Wl1+bl1+part (pre -> hout)
    k_fused<256><<<FUSED_GRID, 128, GEMM_SMEM>>>(
        hf, HID_F, HID_F, wf + 131072, HID_F, part, hf, aggf, NN);
    k_mma_l<true><<<dim3(MT, 2), 128, GEMM_SMEM>>>(
        aggf, HID_F, HID_F, wf + 65536, HID_F, bl1, part, hout, h2f, NN);

    // layer 2 fused GEMM: t2 = h2@Wl2 (fp16) ; tmp = h2@Wr2 + bl2 (fp32)
    k_mma2<<<MT, 128, GEMM_SMEM>>>(
        h2f, HID_F, HID_F, wf + 196608, HID_F, bl2, t2, p_tmp, NN);
    // out = mean-agg(t2) + tmp
    k_agg47_add<<<AGG_BLKS, 256>>>(t2, p_tmp, out);
}

// round 14
// speedup vs baseline: 1.7005x; 1.7005x over previous
#include <cuda_runtime.h>
#include <cuda_fp16.h>
#include <cstdint>

#define NN 100000
#define EE 1600000
#define IN_F 128
#define HID_F 256
#define OUT_F 47
#define T2S 48

// ---------------- scratch ---------------------------------------------------
__device__ float g_tmp[(size_t)NN * T2S];
__device__ __align__(16) __half g_xf  [(size_t)NN * IN_F];
__device__ __align__(16) __half g_aggf[(size_t)NN * HID_F];
__device__ __align__(16) __half g_hf  [(size_t)NN * HID_F];
__device__ __align__(16) __half g_h2f [(size_t)NN * HID_F];
__device__ __align__(16) __half g_part[(size_t)NN * HID_F];
__device__ __align__(16) __half g_t2  [(size_t)NN * T2S];
__device__ int   g_count [NN];
__device__ float g_invdeg[NN];
__device__ int   g_rowptr[NN + 1];
__device__ int   g_cursor[NN];
__device__ int   g_csrsrc[EE];
__device__ int   g_bsums [128];
__device__ int   g_is64;

#define WB_TOTAL 229376
__device__ __align__(16) __half g_wf[WB_TOTAL];

#define MT 782

// ---------------- prep ------------------------------------------------------
__global__ void k_prep(const int* ei_raw,
                       const float* Wl0, const float* Wr0,
                       const float* Wl1, const float* Wr1,
                       const float* Wl2, const float* Wr2) {
    int idx = blockIdx.x * blockDim.x + threadIdx.x;
    if (idx < NN) g_count[idx] = 0;
    if (idx == 0) {
        int is64 = 1;
        for (int i = 0; i < 256; i++)
            if (ei_raw[2 * i + 1] != 0) { is64 = 0; break; }
        g_is64 = is64;
    }
    if (idx < WB_TOTAL) {
        float w;
        if (idx < 32768)       { int l = idx;          int n = l >> 7, k = l & 127; w = Wl0[k * 256 + n]; }
        else if (idx < 65536)  { int l = idx - 32768;  int n = l >> 7, k = l & 127; w = Wr0[k * 256 + n]; }
        else if (idx < 131072) { int l = idx - 65536;  int n = l >> 8, k = l & 255; w = Wl1[k * 256 + n]; }
        else if (idx < 196608) { int l = idx - 131072; int n = l >> 8, k = l & 255; w = Wr1[k * 256 + n]; }
        else if (idx < 212992) { int l = idx - 196608; int n = l >> 8, k = l & 255; w = (n < OUT_F) ? Wl2[k * OUT_F + n] : 0.f; }
        else                   { int l = idx - 212992; int n = l >> 8, k = l & 255; w = (n < OUT_F) ? Wr2[k * OUT_F + n] : 0.f; }
        g_wf[idx] = __float2half_rn(w);
    }
}

__global__ void k_cvt(const float4* __restrict__ X, uint2* __restrict__ O, int n4) {
    int i = blockIdx.x * blockDim.x + threadIdx.x;
    if (i >= n4) return;
    float4 v = X[i];
    __half2 p0 = __floats2half2_rn(v.x, v.y);
    __half2 p1 = __floats2half2_rn(v.z, v.w);
    uint2 o;
    o.x = *(uint32_t*)&p0;
    o.y = *(uint32_t*)&p1;
    O[i] = o;
}

// ---------------- CSR build -------------------------------------------------
__device__ __forceinline__ int load_edge(const void* ei, long long idx, int is64) {
    if (is64) return (int)((const long long*)ei)[idx];
    return ((const int*)ei)[idx];
}

__global__ void k_hist(const void* ei) {
    int e = blockIdx.x * blockDim.x + threadIdx.x;
    if (e < EE) {
        int d = load_edge(ei, (long long)EE + e, g_is64);
        atomicAdd(&g_count[d], 1);
    }
}

__global__ void k_scan1() {
    __shared__ int sh[1024];
    int i = blockIdx.x * 1024 + threadIdx.x;
    int v = (i < NN) ? g_count[i] : 0;
    sh[threadIdx.x] = v;
    __syncthreads();
    for (int off = 1; off < 1024; off <<= 1) {
        int t = (threadIdx.x >= off) ? sh[threadIdx.x - off] : 0;
        __syncthreads();
        sh[threadIdx.x] += t;
        __syncthreads();
    }
    if (i < NN) g_rowptr[i] = sh[threadIdx.x] - v;
    if (threadIdx.x == 1023) g_bsums[blockIdx.x] = sh[1023];
}

__global__ void k_scan23() {
    __shared__ int base;
    if (threadIdx.x == 0) {
        int run = 0;
        for (int b = 0; b < (int)blockIdx.x; b++) run += g_bsums[b];
        base = run;
    }
    __syncthreads();
    int i = blockIdx.x * 1024 + threadIdx.x;
    if (i < NN) {
        int r = g_rowptr[i] + base;
        g_rowptr[i] = r;
        g_cursor[i] = r;
        g_invdeg[i] = 1.0f / (float)max(g_count[i], 1);
    }
    if (i == 0) g_rowptr[NN] = EE;
}

__global__ void k_scatter(const void* ei) {
    int e = blockIdx.x * blockDim.x + threadIdx.x;
    if (e < EE) {
        int is64 = g_is64;
        int d = load_edge(ei, (long long)EE + e, is64);
        int s = load_edge(ei, e, is64);
        int p = atomicAdd(&g_cursor[d], 1);
        g_csrsrc[p] = s;
    }
}

// ---------------- mean aggregation: fp16 -> fp16 plane ------------------------
__global__ void k_agg128(const __half* __restrict__ X, __half* __restrict__ OF) {
    int w = (blockIdx.x * blockDim.x + threadIdx.x) >> 5;
    int lane = threadIdx.x & 31;
    if (w >= NN) return;
    int beg = g_rowptr[w], end = g_rowptr[w + 1];
    float4 acc = make_float4(0.f, 0.f, 0.f, 0.f);
    int e = beg;
    for (; e + 4 <= end; e += 4) {
        int s0 = g_csrsrc[e], s1 = g_csrsrc[e + 1];
        int s2 = g_csrsrc[e + 2], s3 = g_csrsrc[e + 3];
        uint2 u0 = ((const uint2*)(X + (size_t)s0 * IN_F))[lane];
        uint2 u1 = ((const uint2*)(X + (size_t)s1 * IN_F))[lane];
        uint2 u2 = ((const uint2*)(X + (size_t)s2 * IN_F))[lane];
        uint2 u3 = ((const uint2*)(X + (size_t)s3 * IN_F))[lane];
        float2 a0 = __half22float2(*(__half2*)&u0.x), b0 = __half22float2(*(__half2*)&u0.y);
        float2 a1 = __half22float2(*(__half2*)&u1.x), b1 = __half22float2(*(__half2*)&u1.y);
        float2 a2 = __half22float2(*(__half2*)&u2.x), b2 = __half22float2(*(__half2*)&u2.y);
        float2 a3 = __half22float2(*(__half2*)&u3.x), b3 = __half22float2(*(__half2*)&u3.y);
        acc.x += a0.x + a1.x + a2.x + a3.x;
        acc.y += a0.y + a1.y + a2.y + a3.y;
        acc.z += b0.x + b1.x + b2.x + b3.x;
        acc.w += b0.y + b1.y + b2.y + b3.y;
    }
    for (; e < end; e++) {
        uint2 u = ((const uint2*)(X + (size_t)g_csrsrc[e] * IN_F))[lane];
        float2 a = __half22float2(*(__half2*)&u.x), b = __half22float2(*(__half2*)&u.y);
        acc.x += a.x; acc.y += a.y; acc.z += b.x; acc.w += b.y;
    }
    float inv = g_invdeg[w];
    __half2 p0 = __floats2half2_rn(acc.x * inv, acc.y * inv);
    __half2 p1 = __floats2half2_rn(acc.z * inv, acc.w * inv);
    uint2 o;
    o.x = *(uint32_t*)&p0;
    o.y = *(uint32_t*)&p1;
    ((uint2*)(OF + (size_t)w * IN_F))[lane] = o;
}

__global__ void k_agg256(const __half* __restrict__ X, __half* __restrict__ OF) {
    int w = (blockIdx.x * blockDim.x + threadIdx.x) >> 5;
    int lane = threadIdx.x & 31;
    if (w >= NN) return;
    int beg = g_rowptr[w], end = g_rowptr[w + 1];
    float acc[8];
#pragma unroll
    for (int j = 0; j < 8; j++) acc[j] = 0.f;
    int e = beg;
    for (; e + 4 <= end; e += 4) {
        int s0 = g_csrsrc[e], s1 = g_csrsrc[e + 1];
        int s2 = g_csrsrc[e + 2], s3 = g_csrsrc[e + 3];
        uint4 u0 = ((const uint4*)(X + (size_t)s0 * HID_F))[lane];
        uint4 u1 = ((const uint4*)(X + (size_t)s1 * HID_F))[lane];
        uint4 u2 = ((const uint4*)(X + (size_t)s2 * HID_F))[lane];
        uint4 u3 = ((const uint4*)(X + (size_t)s3 * HID_F))[lane];
#pragma unroll
        for (int q = 0; q < 4; q++) {
            uint32_t w0 = (&u0.x)[q], w1 = (&u1.x)[q], w2 = (&u2.x)[q], w3 = (&u3.x)[q];
            float2 f0 = __half22float2(*(__half2*)&w0);
            float2 f1 = __half22float2(*(__half2*)&w1);
            float2 f2 = __half22float2(*(__half2*)&w2);
            float2 f3 = __half22float2(*(__half2*)&w3);
            acc[2 * q]     += f0.x + f1.x + f2.x + f3.x;
            acc[2 * q + 1] += f0.y + f1.y + f2.y + f3.y;
        }
    }
    for (; e < end; e++) {
        uint4 u = ((const uint4*)(X + (size_t)g_csrsrc[e] * HID_F))[lane];
#pragma unroll
        for (int q = 0; q < 4; q++) {
            uint32_t ww = (&u.x)[q];
            float2 f = __half22float2(*(__half2*)&ww);
            acc[2 * q] += f.x; acc[2 * q + 1] += f.y;
        }
    }
    float inv = g_invdeg[w];
    uint4 o;
#pragma unroll
    for (int q = 0; q < 4; q++) {
        __half2 p = __floats2half2_rn(acc[2 * q] * inv, acc[2 * q + 1] * inv);
        (&o.x)[q] = *(uint32_t*)&p;
    }
    ((uint4*)(OF + (size_t)w * HID_F))[lane] = o;
}

// mean-agg over t2 + tmp -> out
__global__ void k_agg47_add(const __half* __restrict__ T2, const float* __restrict__ Tmp,
                            float* __restrict__ out) {
    int w = (blockIdx.x * blockDim.x + threadIdx.x) >> 5;
    int lane = threadIdx.x & 31;
    if (w >= NN || lane >= 24) return;
    int beg = g_rowptr[w], end = g_rowptr[w + 1];
    float a0 = 0.f, a1 = 0.f;
    int e = beg;
    for (; e + 4 <= end; e += 4) {
        int s0 = g_csrsrc[e], s1 = g_csrsrc[e + 1];
        int s2 = g_csrsrc[e + 2], s3 = g_csrsrc[e + 3];
        uint32_t u0 = *(const uint32_t*)(T2 + (size_t)s0 * T2S + lane * 2);
        uint32_t u1 = *(const uint32_t*)(T2 + (size_t)s1 * T2S + lane * 2);
        uint32_t u2 = *(const uint32_t*)(T2 + (size_t)s2 * T2S + lane * 2);
        uint32_t u3 = *(const uint32_t*)(T2 + (size_t)s3 * T2S + lane * 2);
        float2 f0 = __half22float2(*(__half2*)&u0);
        float2 f1 = __half22float2(*(__half2*)&u1);
        float2 f2 = __half22float2(*(__half2*)&u2);
        float2 f3 = __half22float2(*(__half2*)&u3);
        a0 += f0.x + f1.x + f2.x + f3.x;
        a1 += f0.y + f1.y + f2.y + f3.y;
    }
    for (; e < end; e++) {
        uint32_t u = *(const uint32_t*)(T2 + (size_t)g_csrsrc[e] * T2S + lane * 2);
        float2 f = __half22float2(*(__half2*)&u);
        a0 += f.x; a1 += f.y;
    }
    float inv = g_invdeg[w];
    const float* tr = Tmp + (size_t)w * T2S;
    float* orow = out + (size_t)w * OUT_F;
    int c0 = lane * 2, c1 = c0 + 1;
    orow[c0] = a0 * inv + tr[c0];
    if (c1 < OUT_F) orow[c1] = a1 * inv + tr[c1];
}

// ---------------- GEMM building blocks ---------------------------------------
__device__ __forceinline__ void mma16816(float* c, const uint32_t* a, const uint32_t* b) {
    asm volatile(
        "mma.sync.aligned.m16n8k16.row.col.f32.f16.f16.f32 "
        "{%0,%1,%2,%3}, {%4,%5,%6,%7}, {%8,%9}, {%0,%1,%2,%3};"
        : "+f"(c[0]), "+f"(c[1]), "+f"(c[2]), "+f"(c[3])
        : "r"(a[0]), "r"(a[1]), "r"(a[2]), "r"(a[3]), "r"(b[0]), "r"(b[1]));
}
__device__ __forceinline__ void ldmx4(uint32_t& r0, uint32_t& r1, uint32_t& r2, uint32_t& r3,
                                      uint32_t addr) {
    asm volatile("ldmatrix.sync.aligned.m8n8.x4.shared.b16 {%0,%1,%2,%3}, [%4];"
                 : "=r"(r0), "=r"(r1), "=r"(r2), "=r"(r3) : "r"(addr));
}
__device__ __forceinline__ void cp16(uint32_t dst, const void* src) {
    asm volatile("cp.async.cg.shared.global [%0], [%1], 16;" :: "r"(dst), "l"(src));
}
__device__ __forceinline__ void cp_commit() {
    asm volatile("cp.async.commit_group;" ::: "memory");
}
template <int N> __device__ __forceinline__ void cp_wait() {
    asm volatile("cp.async.wait_group %0;" :: "n"(N) : "memory");
}
__device__ __forceinline__ uint32_t smem_u32(const void* p) {
    uint32_t a;
    asm("{ .reg .u64 t; cvta.to.shared.u64 t, %1; cvt.u32.u64 %0, t; }"
        : "=r"(a) : "l"(p));
    return a;
}

#define APL 10240
#define STAGE (2 * APL)
#define GEMM_SMEM (4 * STAGE)

struct GemmCore {
    template <typename EPI>
    static __device__ __forceinline__ void run(
        const __half* A, int ldA, int K, const __half* B, int ldB,
        int rowBase, int colBlk, int M, char* smem, int tid, EPI epi) {
        const uint32_t sbase = smem_u32(smem);
        const int wid  = tid >> 5;
        const int lane = tid & 31;
        const int wm   = wid >> 1;
        const int wn   = wid & 1;
        const uint32_t aoff = (uint32_t)((lane & 15) * 80 + (lane >> 4) * 16);
        const uint32_t boff = (uint32_t)(((lane & 7) + ((lane >> 4) & 1) * 8) * 80 +
                                         ((lane >> 3) & 1) * 16);
        float acc[4][8][4];
#pragma unroll
        for (int mt = 0; mt < 4; mt++)
#pragma unroll
            for (int nt = 0; nt < 8; nt++)
#pragma unroll
                for (int j = 0; j < 4; j++) acc[mt][nt][j] = 0.f;

        const int NC = K / 32;
        auto issue = [&](int c) {
            const uint32_t sb = sbase + (c & 3) * STAGE;
            const int k0 = c * 32;
#pragma unroll
            for (int i = tid; i < 1024; i += 128) {
                int p = i >> 9, r = (i >> 2) & 127, ch = i & 3;
                const __half* g;
                if (p == 0) {
                    int gr = min(rowBase + r, M - 1);
                    g = A + (size_t)gr * ldA + k0 + ch * 8;
                } else {
                    g = B + (size_t)(colBlk + r) * ldB + k0 + ch * 8;
                }
                cp16(sb + p * APL + r * 80 + ch * 16, g);
            }
            cp_commit();
        };

        issue(0);
        issue(1);
        for (int c = 0; c < NC; c++) {
            if (c + 2 < NC)      { issue(c + 2); cp_wait<2>(); }
            else if (c + 1 < NC) { cp_wait<1>(); }
            else                 { cp_wait<0>(); }
            __syncthreads();
            const uint32_t sA = sbase + (c & 3) * STAGE;
            const uint32_t sB = sA + APL;
#pragma unroll
            for (int ks = 0; ks < 2; ks++) {
                const uint32_t kshift = (uint32_t)(ks * 32);
                uint32_t a[4][4];
#pragma unroll
                for (int mt = 0; mt < 4; mt++) {
                    uint32_t addr = sA + (uint32_t)((64 * wm + mt * 16) * 80) + aoff + kshift;
                    ldmx4(a[mt][0], a[mt][1], a[mt][2], a[mt][3], addr);
                }
                uint32_t b[8][2];
#pragma unroll
                for (int ntp = 0; ntp < 4; ntp++) {
                    uint32_t addr = sB + (uint32_t)((64 * wn + ntp * 16) * 80) + boff + kshift;
                    ldmx4(b[2 * ntp][0], b[2 * ntp][1], b[2 * ntp + 1][0], b[2 * ntp + 1][1], addr);
                }
#pragma unroll
                for (int mt = 0; mt < 4; mt++)
#pragma unroll
                    for (int nt = 0; nt < 8; nt++)
                        mma16816(acc[mt][nt], a[mt], b[nt]);
            }
        }

        const int gid = lane >> 2, tig = lane & 3;
#pragma unroll
        for (int mt = 0; mt < 4; mt++) {
            int r0 = rowBase + 64 * wm + mt * 16 + gid;
#pragma unroll
            for (int nt = 0; nt < 8; nt++) {
                int gc = colBlk + 64 * wn + nt * 8 + 2 * tig;
#pragma unroll
                for (int half = 0; half < 2; half++) {
                    int rr = r0 + half * 8;
                    if (rr >= M) continue;
                    epi(rr, gc, acc[mt][nt][half * 2 + 0], acc[mt][nt][half * 2 + 1]);
                }
            }
        }
    }
};

// self-GEMM: A@B -> fp16 partial plane
__global__ void __launch_bounds__(128, 2)
k_self(const __half* __restrict__ A, int ldA, int K,
       const __half* __restrict__ B, int ldB,
       __half* __restrict__ Pout, int M) {
    extern __shared__ __align__(16) char smem[];
    GemmCore::run(A, ldA, K, B, ldB, blockIdx.x * 128, blockIdx.y * 128, M,
                  smem, threadIdx.x,
        [&](int rr, int gc, float v0, float v1) {
            __half2 hp = __floats2half2_rn(v0, v1);
            *(__half2*)(Pout + (size_t)rr * HID_F + gc) = hp;
        });
}

// agg-GEMM: agg@Wl + bias + partial (+pre) -> relu plane
template <bool WPRE>
__global__ void __launch_bounds__(128, 2)
k_mma_l(const __half* __restrict__ A, int ldA, int K,
        const __half* __restrict__ B, int ldB,
        const float* __restrict__ bias, const __half* __restrict__ Part,
        float* __restrict__ Cpre, __half* __restrict__ Ch, int M) {
    extern __shared__ __align__(16) char smem[];
    GemmCore::run(A, ldA, K, B, ldB, blockIdx.x * 128, blockIdx.y * 128, M,
                  smem, threadIdx.x,
        [&](int rr, int gc, float v0, float v1) {
            float2 pv = __half22float2(*(const __half2*)(Part + (size_t)rr * HID_F + gc));
            v0 += bias[gc] + pv.x;
            v1 += bias[gc + 1] + pv.y;
            if (WPRE) {
                float* p = Cpre + (size_t)rr * HID_F + gc;
                p[0] = v0; p[1] = v1;
            }
            v0 = fmaxf(v0, 0.f); v1 = fmaxf(v1, 0.f);
            __half2 hp = __floats2half2_rn(v0, v1);
            *(__half2*)(Ch + (size_t)rr * HID_F + gc) = hp;
        });
}

// layer-2 GEMM: split epilogue
__global__ void __launch_bounds__(128, 2)
k_mma2(const __half* __restrict__ A, int ldA, int K,
       const __half* __restrict__ B, int ldB,
       const float* __restrict__ bias,
       __half* __restrict__ Ct2, float* __restrict__ Caux, int M) {
    extern __shared__ __align__(16) char smem[];
    GemmCore::run(A, ldA, K, B, ldB, blockIdx.x * 128, 0, M, smem, threadIdx.x,
        [&](int rr, int gc, float v0, float v1) {
#pragma unroll
            for (int q = 0; q < 2; q++) {
                int col = gc + q;
                float v = q ? v1 : v0;
                if (col < 64) {
                    if (col < OUT_F) Ct2[(size_t)rr * T2S + col] = __float2half_rn(v);
                } else {
                    int c2 = col - 64;
                    if (c2 < OUT_F) Caux[(size_t)rr * T2S + c2] = v + bias[c2];
                }
            }
        });
}

// ---------------- launch ----------------------------------------------------
extern "C" void kernel_launch(void* const* d_in, const int* in_sizes, int n_in,
                              void* d_out, int out_size) {
    const float* x   = (const float*)d_in[0];
    const void*  ei  = d_in[1];
    const float* Wl0 = (const float*)d_in[2];
    const float* bl0 = (const float*)d_in[3];
    const float* Wr0 = (const float*)d_in[4];
    const float* Wl1 = (const float*)d_in[5];
    const float* bl1 = (const float*)d_in[6];
    const float* Wr1 = (const float*)d_in[7];
    const float* Wl2 = (const float*)d_in[8];
    const float* bl2 = (const float*)d_in[9];
    const float* Wr2 = (const float*)d_in[10];

    float* out  = (float*)d_out;
    float* hout = out + (size_t)NN * OUT_F;

    float* p_tmp;
    __half *xf, *aggf, *hf, *h2f, *part, *t2, *wf;
    cudaGetSymbolAddress((void**)&p_tmp, g_tmp);
    cudaGetSymbolAddress((void**)&xf,   g_xf);
    cudaGetSymbolAddress((void**)&aggf, g_aggf);
    cudaGetSymbolAddress((void**)&hf,   g_hf);
    cudaGetSymbolAddress((void**)&h2f,  g_h2f);
    cudaGetSymbolAddress((void**)&part, g_part);
    cudaGetSymbolAddress((void**)&t2,   g_t2);
    cudaGetSymbolAddress((void**)&wf,   g_wf);

    cudaFuncSetAttribute(k_self, cudaFuncAttributeMaxDynamicSharedMemorySize, GEMM_SMEM);
    cudaFuncSetAttribute(k_mma_l<false>, cudaFuncAttributeMaxDynamicSharedMemorySize, GEMM_SMEM);
    cudaFuncSetAttribute(k_mma_l<true>,  cudaFuncAttributeMaxDynamicSharedMemorySize, GEMM_SMEM);
    cudaFuncSetAttribute(k_mma2, cudaFuncAttributeMaxDynamicSharedMemorySize, GEMM_SMEM);

    const int AGG_BLKS = (NN + 7) / 8;

    // side stream + events (created per call; NOT destroyed — destroying a
    // stream/event that participated in an active capture invalidates it.
    // No device memory is allocated by these objects.)
    cudaStream_t s1;
    cudaStreamCreateWithFlags(&s1, cudaStreamNonBlocking);
    cudaEvent_t evCvt, ev1, evH, ev2;
    cudaEventCreateWithFlags(&evCvt, cudaEventDisableTiming);
    cudaEventCreateWithFlags(&ev1,   cudaEventDisableTiming);
    cudaEventCreateWithFlags(&evH,   cudaEventDisableTiming);
    cudaEventCreateWithFlags(&ev2,   cudaEventDisableTiming);

    // ---- main stream: prep + x planes ----
    k_prep<<<(WB_TOTAL + 255) / 256, 256>>>((const int*)ei, Wl0, Wr0, Wl1, Wr1, Wl2, Wr2);
    k_cvt<<<(NN * IN_F / 4 + 255) / 256, 256>>>((const float4*)x, (uint2*)xf, NN * IN_F / 4);
    cudaEventRecord(evCvt, 0);

    // ---- s1: self0 = x @ Wr0 -> part (overlaps CSR build + agg0) ----
    cudaStreamWaitEvent(s1, evCvt, 0);
    k_self<<<dim3(MT, 2), 128, GEMM_SMEM, s1>>>(xf, IN_F, IN_F, wf + 32768, IN_F, part, NN);
    cudaEventRecord(ev1, s1);

    // ---- main: CSR build + layer-0 aggregation ----
    k_hist<<<(EE + 255) / 256, 256>>>(ei);
    k_scan1<<<(NN + 1023) / 1024, 1024>>>();
    k_scan23<<<(NN + 1023) / 1024, 1024>>>();
    k_scatter<<<(EE + 255) / 256, 256>>>(ei);
    k_agg128<<<AGG_BLKS, 256>>>(xf, aggf);

    // ---- main: layer-0 agg-GEMM (needs part from s1) ----
    cudaStreamWaitEvent(0, ev1, 0);
    k_mma_l<false><<<dim3(MT, 2), 128, GEMM_SMEM>>>(
        aggf, IN_F, IN_F, wf + 0, IN_F, bl0, part, nullptr, hf, NN);
    cudaEventRecord(evH, 0);

    // ---- s1: self1 = h @ Wr1 -> part (overlaps agg1) ----
    cudaStreamWaitEvent(s1, evH, 0);
    k_self<<<dim3(MT, 2), 128, GEMM_SMEM, s1>>>(hf, HID_F, HID_F, wf + 131072, HID_F, part, NN);
    cudaEventRecord(ev2, s1);

    // ---- main: layer-1 aggregation (concurrent with self1) ----
    k_agg256<<<AGG_BLKS, 256>>>(hf, aggf);

    // ---- main: layer-1 agg-GEMM (needs part) ----
    cudaStreamWaitEvent(0, ev2, 0);
    k_mma_l<true><<<dim3(MT, 2), 128, GEMM_SMEM>>>(
        aggf, HID_F, HID_F, wf + 65536, HID_F, bl1, part, hout, h2f, NN);

    // ---- layer 2 ----
    k_mma2<<<MT, 128, GEMM_SMEM>>>(
        h2f, HID_F, HID_F, wf + 196608, HID_F, bl2, t2, p_tmp, NN);
    k_agg47_add<<<AGG_BLKS, 256>>>(t2, p_tmp, out);
}

// round 15
// speedup vs baseline: 1.9741x; 1.1609x over previous
#include <cuda_runtime.h>
#include <cuda_fp16.h>
#include <cstdint>

#define NN 100000
#define EE 1600000
#define IN_F 128
#define HID_F 256
#define OUT_F 47
#define T2S 48

// ---------------- scratch ---------------------------------------------------
__device__ float g_tmp[(size_t)NN * T2S];           // layer-2 direct term (fp32)
__device__ __align__(16) __half g_xf  [(size_t)NN * IN_F];
__device__ __align__(16) __half g_aggf[(size_t)NN * HID_F];
__device__ __align__(16) __half g_hf  [(size_t)NN * HID_F];
__device__ __align__(16) __half g_h2f [(size_t)NN * HID_F];
__device__ __align__(16) __half g_t2  [(size_t)NN * T2S];
__device__ int   g_count [NN];
__device__ float g_invdeg[NN];
__device__ int   g_rowptr[NN + 1];
__device__ int   g_cursor[NN];
__device__ int   g_csrsrc[EE];
__device__ int   g_bsums [128];
__device__ int   g_is64;

// weight table, fp16, transposed [N,K] row-major
#define WB_TOTAL 229376
__device__ __align__(16) __half g_wf[WB_TOTAL];

// ---------------- prep: weights + dtype + count-zero + x->fp16 plane ---------
#define CVT_N4 (NN * IN_F / 4)          // 3,200,000
__global__ void k_prep(const int* ei_raw, const float4* __restrict__ X,
                       uint2* __restrict__ XO,
                       const float* Wl0, const float* Wr0,
                       const float* Wl1, const float* Wr1,
                       const float* Wl2, const float* Wr2) {
    int idx = blockIdx.x * blockDim.x + threadIdx.x;
    if (idx < NN) g_count[idx] = 0;
    if (idx == 0) {
        int is64 = 1;
        for (int i = 0; i < 256; i++)
            if (ei_raw[2 * i + 1] != 0) { is64 = 0; break; }
        g_is64 = is64;
    }
    if (idx < WB_TOTAL) {
        float w;
        if (idx < 32768)       { int l = idx;          int n = l >> 7, k = l & 127; w = Wl0[k * 256 + n]; }
        else if (idx < 65536)  { int l = idx - 32768;  int n = l >> 7, k = l & 127; w = Wr0[k * 256 + n]; }
        else if (idx < 131072) { int l = idx - 65536;  int n = l >> 8, k = l & 255; w = Wl1[k * 256 + n]; }
        else if (idx < 196608) { int l = idx - 131072; int n = l >> 8, k = l & 255; w = Wr1[k * 256 + n]; }
        else if (idx < 212992) { int l = idx - 196608; int n = l >> 8, k = l & 255; w = (n < OUT_F) ? Wl2[k * OUT_F + n] : 0.f; }
        else                   { int l = idx - 212992; int n = l >> 8, k = l & 255; w = (n < OUT_F) ? Wr2[k * OUT_F + n] : 0.f; }
        g_wf[idx] = __float2half_rn(w);
    }
    if (idx < CVT_N4) {
        float4 v = X[idx];
        __half2 p0 = __floats2half2_rn(v.x, v.y);
        __half2 p1 = __floats2half2_rn(v.z, v.w);
        uint2 o;
        o.x = *(uint32_t*)&p0;
        o.y = *(uint32_t*)&p1;
        XO[idx] = o;
    }
}

// ---------------- CSR build -------------------------------------------------
__device__ __forceinline__ int load_edge(const void* ei, long long idx, int is64) {
    if (is64) return (int)((const long long*)ei)[idx];
    return ((const int*)ei)[idx];
}

__global__ void k_hist(const void* ei) {
    int e = blockIdx.x * blockDim.x + threadIdx.x;
    if (e < EE) {
        int d = load_edge(ei, (long long)EE + e, g_is64);
        atomicAdd(&g_count[d], 1);
    }
}

__global__ void k_scan1() {
    __shared__ int sh[1024];
    int i = blockIdx.x * 1024 + threadIdx.x;
    int v = (i < NN) ? g_count[i] : 0;
    sh[threadIdx.x] = v;
    __syncthreads();
    for (int off = 1; off < 1024; off <<= 1) {
        int t = (threadIdx.x >= off) ? sh[threadIdx.x - off] : 0;
        __syncthreads();
        sh[threadIdx.x] += t;
        __syncthreads();
    }
    if (i < NN) g_rowptr[i] = sh[threadIdx.x] - v;
    if (threadIdx.x == 1023) g_bsums[blockIdx.x] = sh[1023];
}

__global__ void k_scan23() {
    __shared__ int base;
    if (threadIdx.x == 0) {
        int run = 0;
        for (int b = 0; b < (int)blockIdx.x; b++) run += g_bsums[b];
        base = run;
    }
    __syncthreads();
    int i = blockIdx.x * 1024 + threadIdx.x;
    if (i < NN) {
        int r = g_rowptr[i] + base;
        g_rowptr[i] = r;
        g_cursor[i] = r;
        g_invdeg[i] = 1.0f / (float)max(g_count[i], 1);
    }
    if (i == 0) g_rowptr[NN] = EE;
}

__global__ void k_scatter(const void* ei) {
    int e = blockIdx.x * blockDim.x + threadIdx.x;
    if (e < EE) {
        int is64 = g_is64;
        int d = load_edge(ei, (long long)EE + e, is64);
        int s = load_edge(ei, e, is64);
        int p = atomicAdd(&g_cursor[d], 1);
        g_csrsrc[p] = s;
    }
}

// ---------------- mean aggregation: fp16 -> fp16 plane ------------------------
__global__ void k_agg128(const __half* __restrict__ X, __half* __restrict__ OF) {
    int w = (blockIdx.x * blockDim.x + threadIdx.x) >> 5;
    int lane = threadIdx.x & 31;
    if (w >= NN) return;
    int beg = g_rowptr[w], end = g_rowptr[w + 1];
    float4 acc = make_float4(0.f, 0.f, 0.f, 0.f);
    int e = beg;
    for (; e + 4 <= end; e += 4) {
        int s0 = g_csrsrc[e], s1 = g_csrsrc[e + 1];
        int s2 = g_csrsrc[e + 2], s3 = g_csrsrc[e + 3];
        uint2 u0 = ((const uint2*)(X + (size_t)s0 * IN_F))[lane];
        uint2 u1 = ((const uint2*)(X + (size_t)s1 * IN_F))[lane];
        uint2 u2 = ((const uint2*)(X + (size_t)s2 * IN_F))[lane];
        uint2 u3 = ((const uint2*)(X + (size_t)s3 * IN_F))[lane];
        float2 a0 = __half22float2(*(__half2*)&u0.x), b0 = __half22float2(*(__half2*)&u0.y);
        float2 a1 = __half22float2(*(__half2*)&u1.x), b1 = __half22float2(*(__half2*)&u1.y);
        float2 a2 = __half22float2(*(__half2*)&u2.x), b2 = __half22float2(*(__half2*)&u2.y);
        float2 a3 = __half22float2(*(__half2*)&u3.x), b3 = __half22float2(*(__half2*)&u3.y);
        acc.x += a0.x + a1.x + a2.x + a3.x;
        acc.y += a0.y + a1.y + a2.y + a3.y;
        acc.z += b0.x + b1.x + b2.x + b3.x;
        acc.w += b0.y + b1.y + b2.y + b3.y;
    }
    for (; e < end; e++) {
        uint2 u = ((const uint2*)(X + (size_t)g_csrsrc[e] * IN_F))[lane];
        float2 a = __half22float2(*(__half2*)&u.x), b = __half22float2(*(__half2*)&u.y);
        acc.x += a.x; acc.y += a.y; acc.z += b.x; acc.w += b.y;
    }
    float inv = g_invdeg[w];
    __half2 p0 = __floats2half2_rn(acc.x * inv, acc.y * inv);
    __half2 p1 = __floats2half2_rn(acc.z * inv, acc.w * inv);
    uint2 o;
    o.x = *(uint32_t*)&p0;
    o.y = *(uint32_t*)&p1;
    ((uint2*)(OF + (size_t)w * IN_F))[lane] = o;
}

__global__ void k_agg256(const __half* __restrict__ X, __half* __restrict__ OF) {
    int w = (blockIdx.x * blockDim.x + threadIdx.x) >> 5;
    int lane = threadIdx.x & 31;
    if (w >= NN) return;
    int beg = g_rowptr[w], end = g_rowptr[w + 1];
    float acc[8];
#pragma unroll
    for (int j = 0; j < 8; j++) acc[j] = 0.f;
    int e = beg;
    for (; e + 4 <= end; e += 4) {
        int s0 = g_csrsrc[e], s1 = g_csrsrc[e + 1];
        int s2 = g_csrsrc[e + 2], s3 = g_csrsrc[e + 3];
        uint4 u0 = ((const uint4*)(X + (size_t)s0 * HID_F))[lane];
        uint4 u1 = ((const uint4*)(X + (size_t)s1 * HID_F))[lane];
        uint4 u2 = ((const uint4*)(X + (size_t)s2 * HID_F))[lane];
        uint4 u3 = ((const uint4*)(X + (size_t)s3 * HID_F))[lane];
#pragma unroll
        for (int q = 0; q < 4; q++) {
            uint32_t w0 = (&u0.x)[q], w1 = (&u1.x)[q], w2 = (&u2.x)[q], w3 = (&u3.x)[q];
            float2 f0 = __half22float2(*(__half2*)&w0);
            float2 f1 = __half22float2(*(__half2*)&w1);
            float2 f2 = __half22float2(*(__half2*)&w2);
            float2 f3 = __half22float2(*(__half2*)&w3);
            acc[2 * q]     += f0.x + f1.x + f2.x + f3.x;
            acc[2 * q + 1] += f0.y + f1.y + f2.y + f3.y;
        }
    }
    for (; e < end; e++) {
        uint4 u = ((const uint4*)(X + (size_t)g_csrsrc[e] * HID_F))[lane];
#pragma unroll
        for (int q = 0; q < 4; q++) {
            uint32_t ww = (&u.x)[q];
            float2 f = __half22float2(*(__half2*)&ww);
            acc[2 * q] += f.x; acc[2 * q + 1] += f.y;
        }
    }
    float inv = g_invdeg[w];
    uint4 o;
#pragma unroll
    for (int q = 0; q < 4; q++) {
        __half2 p = __floats2half2_rn(acc[2 * q] * inv, acc[2 * q + 1] * inv);
        (&o.x)[q] = *(uint32_t*)&p;
    }
    ((uint4*)(OF + (size_t)w * HID_F))[lane] = o;
}

// mean-agg over t2 (fp16, stride T2S) + tmp (fp32) -> out (stride 47)
__global__ void k_agg47_add(const __half* __restrict__ T2, const float* __restrict__ Tmp,
                            float* __restrict__ out) {
    int w = (blockIdx.x * blockDim.x + threadIdx.x) >> 5;
    int lane = threadIdx.x & 31;
    if (w >= NN || lane >= 24) return;
    int beg = g_rowptr[w], end = g_rowptr[w + 1];
    float a0 = 0.f, a1 = 0.f;
    int e = beg;
    for (; e + 4 <= end; e += 4) {
        int s0 = g_csrsrc[e], s1 = g_csrsrc[e + 1];
        int s2 = g_csrsrc[e + 2], s3 = g_csrsrc[e + 3];
        uint32_t u0 = *(const uint32_t*)(T2 + (size_t)s0 * T2S + lane * 2);
        uint32_t u1 = *(const uint32_t*)(T2 + (size_t)s1 * T2S + lane * 2);
        uint32_t u2 = *(const uint32_t*)(T2 + (size_t)s2 * T2S + lane * 2);
        uint32_t u3 = *(const uint32_t*)(T2 + (size_t)s3 * T2S + lane * 2);
        float2 f0 = __half22float2(*(__half2*)&u0);
        float2 f1 = __half22float2(*(__half2*)&u1);
        float2 f2 = __half22float2(*(__half2*)&u2);
        float2 f3 = __half22float2(*(__half2*)&u3);
        a0 += f0.x + f1.x + f2.x + f3.x;
        a1 += f0.y + f1.y + f2.y + f3.y;
    }
    for (; e < end; e++) {
        uint32_t u = *(const uint32_t*)(T2 + (size_t)g_csrsrc[e] * T2S + lane * 2);
        float2 f = __half22float2(*(__half2*)&u);
        a0 += f.x; a1 += f.y;
    }
    float inv = g_invdeg[w];
    const float* tr = Tmp + (size_t)w * T2S;
    float* orow = out + (size_t)w * OUT_F;
    int c0 = lane * 2, c1 = c0 + 1;
    orow[c0] = a0 * inv + tr[c0];
    if (c1 < OUT_F) orow[c1] = a1 * inv + tr[c1];
}

// ---------------- GEMM: fp16, ldmatrix feeds, 4-stage cp.async ---------------
__device__ __forceinline__ void mma16816(float* c, const uint32_t* a, const uint32_t* b) {
    asm volatile(
        "mma.sync.aligned.m16n8k16.row.col.f32.f16.f16.f32 "
        "{%0,%1,%2,%3}, {%4,%5,%6,%7}, {%8,%9}, {%0,%1,%2,%3};"
        : "+f"(c[0]), "+f"(c[1]), "+f"(c[2]), "+f"(c[3])
        : "r"(a[0]), "r"(a[1]), "r"(a[2]), "r"(a[3]), "r"(b[0]), "r"(b[1]));
}
__device__ __forceinline__ void ldmx4(uint32_t& r0, uint32_t& r1, uint32_t& r2, uint32_t& r3,
                                      uint32_t addr) {
    asm volatile("ldmatrix.sync.aligned.m8n8.x4.shared.b16 {%0,%1,%2,%3}, [%4];"
                 : "=r"(r0), "=r"(r1), "=r"(r2), "=r"(r3) : "r"(addr));
}
__device__ __forceinline__ void cp16(uint32_t dst, const void* src) {
    asm volatile("cp.async.cg.shared.global [%0], [%1], 16;" :: "r"(dst), "l"(src));
}
__device__ __forceinline__ void cp_commit() {
    asm volatile("cp.async.commit_group;" ::: "memory");
}
template <int N> __device__ __forceinline__ void cp_wait() {
    asm volatile("cp.async.wait_group %0;" :: "n"(N) : "memory");
}
__device__ __forceinline__ uint32_t smem_u32(const void* p) {
    uint32_t a;
    asm("{ .reg .u64 t; cvta.to.shared.u64 t, %1; cvt.u32.u64 %0, t; }"
        : "=r"(a) : "l"(p));
    return a;
}

#define APL 10240                        // plane: 128 rows x 80B (64B payload)
#define STAGE (2 * APL)                  // A, B
#define GEMM_SMEM (4 * STAGE)            // 81920 (4 stages)

template <bool DUAL, bool BIAS, bool RELU, bool WPLANES, bool WPRE, bool SPLIT2>
__global__ void __launch_bounds__(128, 2)
k_mma(const __half* __restrict__ A1, int ldA1, int K1,
      const __half* __restrict__ B1, int ldB1,
      const __half* __restrict__ A2, int ldA2, int K2,
      const __half* __restrict__ B2, int ldB2,
      const float* __restrict__ bias,
      __half* __restrict__ Ch, int ldC, float* __restrict__ Cpre,
      __half* __restrict__ Ct2, float* __restrict__ Caux, int M) {
    extern __shared__ __align__(16) char smem[];
    const uint32_t sbase = smem_u32(smem);

    const int tid  = threadIdx.x;
    const int wid  = tid >> 5;
    const int lane = tid & 31;
    const int wm   = wid >> 1;
    const int wn   = wid & 1;
    const int gid  = lane >> 2;
    const int tig  = lane & 3;

    const int rowBase = blockIdx.x * 128;
    const int colBlk  = blockIdx.y * 128;

    const uint32_t aoff = (uint32_t)((lane & 15) * 80 + (lane >> 4) * 16);
    const uint32_t boff = (uint32_t)(((lane & 7) + ((lane >> 4) & 1) * 8) * 80 +
                                     ((lane >> 3) & 1) * 16);

    float acc[4][8][4];
#pragma unroll
    for (int mt = 0; mt < 4; mt++)
#pragma unroll
        for (int nt = 0; nt < 8; nt++)
#pragma unroll
            for (int j = 0; j < 4; j++) acc[mt][nt][j] = 0.f;

    const int NC1 = K1 / 32;
    const int NC  = DUAL ? NC1 + K2 / 32 : NC1;

    auto issue = [&](int c) {
        const uint32_t sb = sbase + (c & 3) * STAGE;
        const int seg = (DUAL && c >= NC1) ? 1 : 0;
        const int k0 = (c - (seg ? NC1 : 0)) * 32;
        const __half* A = seg ? A2 : A1;
        const __half* B = seg ? B2 : B1;
        const int ldA = seg ? ldA2 : ldA1;
        const int ldB = seg ? ldB2 : ldB1;
#pragma unroll
        for (int i = tid; i < 1024; i += 128) {
            int p = i >> 9, r = (i >> 2) & 127, ch = i & 3;
            const __half* g;
            if (p == 0) {
                int gr = min(rowBase + r, M - 1);
                g = A + (size_t)gr * ldA + k0 + ch * 8;
            } else {
                g = B + (size_t)(colBlk + r) * ldB + k0 + ch * 8;
            }
            cp16(sb + p * APL + r * 80 + ch * 16, g);
        }
        cp_commit();
    };

    issue(0);
    issue(1);
    for (int c = 0; c < NC; c++) {
        if (c + 2 < NC)      { issue(c + 2); cp_wait<2>(); }
        else if (c + 1 < NC) { cp_wait<1>(); }
        else                 { cp_wait<0>(); }
        __syncthreads();
        const uint32_t sA = sbase + (c & 3) * STAGE;
        const uint32_t sB = sA + APL;
#pragma unroll
        for (int ks = 0; ks < 2; ks++) {
            const uint32_t kshift = (uint32_t)(ks * 32);
            uint32_t a[4][4];
#pragma unroll
            for (int mt = 0; mt < 4; mt++) {
                uint32_t addr = sA + (uint32_t)((64 * wm + mt * 16) * 80) + aoff + kshift;
                ldmx4(a[mt][0], a[mt][1], a[mt][2], a[mt][3], addr);
            }
            uint32_t b[8][2];
#pragma unroll
            for (int ntp = 0; ntp < 4; ntp++) {
                uint32_t addr = sB + (uint32_t)((64 * wn + ntp * 16) * 80) + boff + kshift;
                ldmx4(b[2 * ntp][0], b[2 * ntp][1], b[2 * ntp + 1][0], b[2 * ntp + 1][1], addr);
            }
#pragma unroll
            for (int mt = 0; mt < 4; mt++)
#pragma unroll
                for (int nt = 0; nt < 8; nt++)
                    mma16816(acc[mt][nt], a[mt], b[nt]);
        }
    }

    // ---- epilogue ----
#pragma unroll
    for (int mt = 0; mt < 4; mt++) {
        int r0 = rowBase + 64 * wm + mt * 16 + gid;
#pragma unroll
        for (int nt = 0; nt < 8; nt++) {
            int gc = colBlk + 64 * wn + nt * 8 + 2 * tig;
#pragma unroll
            for (int half = 0; half < 2; half++) {
                int rr = r0 + half * 8;
                if (rr >= M) continue;
                float v0 = acc[mt][nt][half * 2 + 0];
                float v1 = acc[mt][nt][half * 2 + 1];
                if (SPLIT2) {
#pragma unroll
                    for (int q = 0; q < 2; q++) {
                        int col = gc + q;
                        float v = q ? v1 : v0;
                        if (col < 64) {
                            if (col < OUT_F) Ct2[(size_t)rr * T2S + col] = __float2half_rn(v);
                        } else {
                            int c2 = col - 64;
                            if (c2 < OUT_F) Caux[(size_t)rr * T2S + c2] = v + bias[c2];
                        }
                    }
                } else {
                    if (BIAS) { v0 += bias[gc]; v1 += bias[gc + 1]; }
                    if (WPRE) {
                        float* p = Cpre + (size_t)rr * ldC + gc;
                        p[0] = v0; p[1] = v1;
                    }
                    if (RELU) { v0 = fmaxf(v0, 0.f); v1 = fmaxf(v1, 0.f); }
                    if (WPLANES) {
                        __half2 hp = __floats2half2_rn(v0, v1);
                        *(__half2*)(Ch + (size_t)rr * ldC + gc) = hp;
                    }
                }
            }
        }
    }
}

// ---------------- launch ----------------------------------------------------
extern "C" void kernel_launch(void* const* d_in, const int* in_sizes, int n_in,
                              void* d_out, int out_size) {
    const float* x   = (const float*)d_in[0];
    const void*  ei  = d_in[1];
    const float* Wl0 = (const float*)d_in[2];
    const float* bl0 = (const float*)d_in[3];
    const float* Wr0 = (const float*)d_in[4];
    const float* Wl1 = (const float*)d_in[5];
    const float* bl1 = (const float*)d_in[6];
    const float* Wr1 = (const float*)d_in[7];
    const float* Wl2 = (const float*)d_in[8];
    const float* bl2 = (const float*)d_in[9];
    const float* Wr2 = (const float*)d_in[10];

    float* out  = (float*)d_out;
    float* hout = out + (size_t)NN * OUT_F;

    float* p_tmp;
    __half *xf, *aggf, *hf, *h2f, *t2, *wf;
    cudaGetSymbolAddress((void**)&p_tmp, g_tmp);
    cudaGetSymbolAddress((void**)&xf,   g_xf);
    cudaGetSymbolAddress((void**)&aggf, g_aggf);
    cudaGetSymbolAddress((void**)&hf,   g_hf);
    cudaGetSymbolAddress((void**)&h2f,  g_h2f);
    cudaGetSymbolAddress((void**)&t2,   g_t2);
    cudaGetSymbolAddress((void**)&wf,   g_wf);

    cudaFuncSetAttribute(k_mma<true,  true, true,  true,  false, false>,
                         cudaFuncAttributeMaxDynamicSharedMemorySize, GEMM_SMEM);
    cudaFuncSetAttribute(k_mma<true,  true, true,  true,  true,  false>,
                         cudaFuncAttributeMaxDynamicSharedMemorySize, GEMM_SMEM);
    cudaFuncSetAttribute(k_mma<false, true, false, false, false, true>,
                         cudaFuncAttributeMaxDynamicSharedMemorySize, GEMM_SMEM);

    const int MT = (NN + 127) / 128;               // 782
    const int AGG_BLKS = (NN + 7) / 8;

    // fused prep (weights + count-zero + dtype detect + x->fp16) then CSR build
    k_prep<<<(CVT_N4 + 255) / 256, 256>>>((const int*)ei, (const float4*)x, (uint2*)xf,
                                          Wl0, Wr0, Wl1, Wr1, Wl2, Wr2);
    k_hist<<<(EE + 255) / 256, 256>>>(ei);
    k_scan1<<<(NN + 1023) / 1024, 1024>>>();
    k_scan23<<<(NN + 1023) / 1024, 1024>>>();
    k_scatter<<<(EE + 255) / 256, 256>>>(ei);

    // layer 0: relu(agg(x)@Wl0 + bl0 + x@Wr0) -> hf plane
    k_agg128<<<AGG_BLKS, 256>>>(xf, aggf);
    k_mma<true, true, true, true, false, false><<<dim3(MT, 2), 128, GEMM_SMEM>>>(
        aggf, IN_F, IN_F, wf + 0,     IN_F,
        xf,   IN_F, IN_F, wf + 32768, IN_F,
        bl0, hf, HID_F, nullptr, nullptr, nullptr, NN);

    // layer 1: pre -> hout (fp32); relu -> h2f plane
    k_agg256<<<AGG_BLKS, 256>>>(hf, aggf);
    k_mma<true, true, true, true, true, false><<<dim3(MT, 2), 128, GEMM_SMEM>>>(
        aggf, HID_F, HID_F, wf + 65536,  HID_F,
        hf,   HID_F, HID_F, wf + 131072, HID_F,
        bl1, h2f, HID_F, hout, nullptr, nullptr, NN);

    // layer 2 fused: t2 = h2@Wl2 (fp16) ; tmp = h2@Wr2 + bl2 (fp32)
    k_mma<false, true, false, false, false, true><<<dim3(MT, 1), 128, GEMM_SMEM>>>(
        h2f, HID_F, HID_F, wf + 196608, HID_F,
        nullptr, 0, 0, nullptr, 0,
        bl2, nullptr, T2S, nullptr, t2, p_tmp, NN);
    // out = mean-agg(t2) + tmp
    k_agg47_add<<<AGG_BLKS, 256>>>(t2, p_tmp, out);
}